// round 5
// baseline (speedup 1.0000x reference)
#include <cuda_runtime.h>

#define TSEQ 512
#define INF  14
#define HID  8

typedef unsigned long long ull;

__device__ __forceinline__ ull pk(float lo, float hi){
    ull r; asm("mov.b64 %0, {%1,%2};" : "=l"(r) : "f"(lo), "f"(hi)); return r;
}
__device__ __forceinline__ float2 upk(ull v){
    float2 r; asm("mov.b64 {%0,%1}, %2;" : "=f"(r.x), "=f"(r.y) : "l"(v)); return r;
}
__device__ __forceinline__ ull ffma2(ull a, ull b, ull c){
    ull d; asm("fma.rn.f32x2 %0, %1, %2, %3;" : "=l"(d) : "l"(a), "l"(b), "l"(c)); return d;
}
__device__ __forceinline__ float tanhx(float x){
    float r; asm("tanh.approx.f32 %0, %1;" : "=f"(r) : "f"(x)); return r;
}
__device__ __forceinline__ float sigx(float x){
    return fmaf(0.5f, tanhx(0.5f * x), 0.5f);
}

// 4 batch elements per warp (8 lanes each); lane owns h-index j, all 4 gate rows.
// Software-pipelined: each iteration computes L2(t) and L1(t+1) as two
// independent dependency chains sharing one set of h1(t) broadcasts.
__global__ __launch_bounds__(32) void lstm_forex_kernel(
    const float* __restrict__ x,
    const float* __restrict__ Wih1, const float* __restrict__ Whh1,
    const float* __restrict__ bih1, const float* __restrict__ bhh1,
    const float* __restrict__ Wih2, const float* __restrict__ Whh2,
    const float* __restrict__ bih2, const float* __restrict__ bhh2,
    const float* __restrict__ bn_gamma, const float* __restrict__ bn_beta,
    const float* __restrict__ bn_mean, const float* __restrict__ bn_var,
    const float* __restrict__ w1, const float* __restrict__ b1,
    const float* __restrict__ w2, const float* __restrict__ b2,
    float* __restrict__ out, int Bn)
{
    const int lane = threadIdx.x & 31;
    const int j    = lane & 7;
    const int base = lane & 24;
    const int e    = blockIdx.x * 4 + (lane >> 3);
    const bool valid = (e < Bn);
    const int ec = valid ? e : (Bn > 0 ? Bn - 1 : 0);
    const unsigned FULL = 0xffffffffu;

    // ---- packed per-lane weights (gate rows j, j+8, j+16, j+24) ----
    ull wxp[4][7];    // (Wih1[row][2k], Wih1[row][2k+1])
    ull wh1p[4][4];   // (Whh1[row][2k], Whh1[row][2k+1])
    ull wl2p[4][8];   // (Wih2[row][k],  Whh2[row][k])
    ull pb1[4], pb2[4];
#pragma unroll
    for (int g = 0; g < 4; g++){
        const int row = g * 8 + j;
#pragma unroll
        for (int k = 0; k < 7; k++)
            wxp[g][k] = pk(Wih1[row * 14 + 2*k], Wih1[row * 14 + 2*k + 1]);
#pragma unroll
        for (int k = 0; k < 4; k++)
            wh1p[g][k] = pk(Whh1[row * 8 + 2*k], Whh1[row * 8 + 2*k + 1]);
#pragma unroll
        for (int k = 0; k < 8; k++)
            wl2p[g][k] = pk(Wih2[row * 8 + k], Whh2[row * 8 + k]);
        pb1[g] = pk(bih1[row] + bhh1[row], 0.f);
        pb2[g] = pk(bih2[row] + bhh2[row], 0.f);
    }

    // x[e, t, :]: 14 floats = 7 packed pairs
    const ull* px = reinterpret_cast<const ull*>(x) + (size_t)ec * (TSEQ * INF / 2);
    ull xb[7];
#pragma unroll
    for (int k = 0; k < 7; k++) xb[k] = px[k];
    px += 7;

    float h1 = 0.f, c1 = 0.f, h2 = 0.f, c2 = 0.f;

    // ---- prologue: h1(0) from x(0) (h1(-1)=0 -> recurrent term vanishes) ----
    {
        ull a0 = pb1[0], a1 = pb1[1], a2 = pb1[2], a3 = pb1[3];
#pragma unroll
        for (int k = 0; k < 7; k++){
            a0 = ffma2(wxp[0][k], xb[k], a0);
            a1 = ffma2(wxp[1][k], xb[k], a1);
            a2 = ffma2(wxp[2][k], xb[k], a2);
            a3 = ffma2(wxp[3][k], xb[k], a3);
        }
        const float2 u0 = upk(a0), u1 = upk(a1), u2 = upk(a2), u3 = upk(a3);
        const float ai = sigx(u0.x + u0.y);
        const float ag = tanhx(u2.x + u2.y);
        const float ao = sigx(u3.x + u3.y);
        c1 = ai * ag;                       // f*0 = 0
        h1 = ao * tanhx(c1);
    }
    // xb <- x(1)
#pragma unroll
    for (int k = 0; k < 7; k++) xb[k] = px[k];
    px += 7;

#pragma unroll 1
    for (int t = 0; t < TSEQ; t++){
        // shared broadcasts: h1(t) and h2(t-1)
        float hbv[8], gbv[8];
#pragma unroll
        for (int k = 0; k < 8; k++){
            hbv[k] = __shfl_sync(FULL, h1, base + k);
            gbv[k] = __shfl_sync(FULL, h2, base + k);
        }

        // ---- chain A: layer 2 at time t -> h2(t) ----
        ull aA0 = pb2[0], aA1 = pb2[1], aA2 = pb2[2], aA3 = pb2[3];
#pragma unroll
        for (int k = 0; k < 8; k++){
            const ull hp = pk(hbv[k], gbv[k]);
            aA0 = ffma2(wl2p[0][k], hp, aA0);
            aA1 = ffma2(wl2p[1][k], hp, aA1);
            aA2 = ffma2(wl2p[2][k], hp, aA2);
            aA3 = ffma2(wl2p[3][k], hp, aA3);
        }

        // ---- chain B: layer 1 at time t+1 -> h1(t+1) ----
        ull aB0 = pb1[0], aB1 = pb1[1], aB2 = pb1[2], aB3 = pb1[3];
#pragma unroll
        for (int k = 0; k < 7; k++){
            aB0 = ffma2(wxp[0][k], xb[k], aB0);
            aB1 = ffma2(wxp[1][k], xb[k], aB1);
            aB2 = ffma2(wxp[2][k], xb[k], aB2);
            aB3 = ffma2(wxp[3][k], xb[k], aB3);
        }
#pragma unroll
        for (int k = 0; k < 4; k++){
            const ull hp = pk(hbv[2*k], hbv[2*k + 1]);
            aB0 = ffma2(wh1p[0][k], hp, aB0);
            aB1 = ffma2(wh1p[1][k], hp, aB1);
            aB2 = ffma2(wh1p[2][k], hp, aB2);
            aB3 = ffma2(wh1p[3][k], hp, aB3);
        }

        // prefetch x(t+2)
        if (t + 2 < TSEQ){
#pragma unroll
            for (int k = 0; k < 7; k++) xb[k] = px[k];
            px += 7;
        }

        // ---- activations A -> h2(t), c2 ----
        {
            const float2 u0 = upk(aA0), u1 = upk(aA1), u2 = upk(aA2), u3 = upk(aA3);
            const float ai = sigx(u0.x + u0.y);
            const float af = sigx(u1.x + u1.y);
            const float ag = tanhx(u2.x + u2.y);
            const float ao = sigx(u3.x + u3.y);
            c2 = fmaf(af, c2, ai * ag);
            h2 = ao * tanhx(c2);
        }
        // ---- activations B -> h1(t+1), c1 ----
        {
            const float2 u0 = upk(aB0), u1 = upk(aB1), u2 = upk(aB2), u3 = upk(aB3);
            const float ai = sigx(u0.x + u0.y);
            const float af = sigx(u1.x + u1.y);
            const float ag = tanhx(u2.x + u2.y);
            const float ao = sigx(u3.x + u3.y);
            c1 = fmaf(af, c1, ai * ag);
            h1 = ao * tanhx(c1);
        }
        // (last iteration's h1/c1 update is dead work; h2(511) is what we keep)
    }

    // ---------------- epilogue: BatchNorm (eval) + MLP head ----------------
    const float scale = bn_gamma[j] * rsqrtf(bn_var[j] + 1e-5f);
    const float nrm   = fmaf(h2 - bn_mean[j], scale, bn_beta[j]);

    float p0 = w1[0 * 8 + j] * nrm;
    float p1 = w1[1 * 8 + j] * nrm;
    float p2 = w1[2 * 8 + j] * nrm;
    float p3 = w1[3 * 8 + j] * nrm;
#pragma unroll
    for (int off = 4; off > 0; off >>= 1){
        p0 += __shfl_xor_sync(FULL, p0, off);
        p1 += __shfl_xor_sync(FULL, p1, off);
        p2 += __shfl_xor_sync(FULL, p2, off);
        p3 += __shfl_xor_sync(FULL, p3, off);
    }
    if (valid && j == 0){
        float o = b2[0];
        o = fmaf(w2[0], fmaxf(p0 + b1[0], 0.f), o);
        o = fmaf(w2[1], fmaxf(p1 + b1[1], 0.f), o);
        o = fmaf(w2[2], fmaxf(p2 + b1[2], 0.f), o);
        o = fmaf(w2[3], fmaxf(p3 + b1[3], 0.f), o);
        out[e] = o;
    }
}

extern "C" void kernel_launch(void* const* d_in, const int* in_sizes, int n_in,
                              void* d_out, int out_size)
{
    const float* x        = (const float*)d_in[0];
    const float* Wih1     = (const float*)d_in[1];
    const float* Whh1     = (const float*)d_in[2];
    const float* bih1     = (const float*)d_in[3];
    const float* bhh1     = (const float*)d_in[4];
    const float* Wih2     = (const float*)d_in[5];
    const float* Whh2     = (const float*)d_in[6];
    const float* bih2     = (const float*)d_in[7];
    const float* bhh2     = (const float*)d_in[8];
    const float* bn_gamma = (const float*)d_in[9];
    const float* bn_beta  = (const float*)d_in[10];
    const float* bn_mean  = (const float*)d_in[11];
    const float* bn_var   = (const float*)d_in[12];
    const float* w1       = (const float*)d_in[13];
    const float* b1       = (const float*)d_in[14];
    const float* w2       = (const float*)d_in[15];
    const float* b2       = (const float*)d_in[16];

    const int Bn = in_sizes[0] / (TSEQ * INF);
    const int grid = (Bn + 3) / 4;            // 4 batch elements per warp, 1 warp/block

    lstm_forex_kernel<<<grid, 32>>>(x, Wih1, Whh1, bih1, bhh1,
                                    Wih2, Whh2, bih2, bhh2,
                                    bn_gamma, bn_beta, bn_mean, bn_var,
                                    w1, b1, w2, b2,
                                    (float*)d_out, Bn);
}